// round 4
// baseline (speedup 1.0000x reference)
#include <cuda_runtime.h>
#include <cuda_bf16.h>
#include <math.h>

// Problem constants (from reference): H=8, D=16 -> HD=128
#define HD 128
#define MAX_N 100000

// Scratch for segment_sum result: [N, H, D] floats = 51.2 MB (fits in L2)
__device__ float g_nft[(size_t)MAX_N * HD];

// ---------------------------------------------------------------------------
// Edge kernel: one warp per edge.
// Lane l holds float4 = elements [l*4, l*4+4) of the 128-wide (h*16+d) row.
// head(l) = l >> 2 ; the 16 elements of one head span 4 consecutive lanes.
// ---------------------------------------------------------------------------
__global__ void edge_kernel(const float* __restrict__ eft,
                            const float* __restrict__ node,
                            const int*   __restrict__ dst,
                            float*       __restrict__ a_out,   // may be null
                            float*       __restrict__ nft,
                            int E)
{
    int gw   = (blockIdx.x * blockDim.x + threadIdx.x) >> 5;   // global warp = edge id
    int lane = threadIdx.x & 31;
    if (gw >= E) return;

    int d = __ldg(&dst[gw]);   // broadcast (same addr all lanes -> L1 broadcast)

    const float4* ep = (const float4*)(eft  + (size_t)gw * HD);
    const float4* np = (const float4*)(node + (size_t)d  * HD);
    float4 ev = __ldcs(ep + lane);   // streaming: read-once, keep L2 for node/nft
    float4 nv = __ldg (np + lane);   // reused across edges -> cache normally

    // per-lane partial dot (4 of the 16 d's of this lane's head)
    float p = ev.x * nv.x + ev.y * nv.y + ev.z * nv.z + ev.w * nv.w;
    // reduce within the 4-lane head group
    p += __shfl_xor_sync(0xffffffffu, p, 1);
    p += __shfl_xor_sync(0xffffffffu, p, 2);
    // p = sim[e, head(lane)] on every lane of the group

    // softmax across the 8 heads (values live on lanes 0,4,8,...,28)
    float mx = p;
    #pragma unroll
    for (int k = 0; k < 8; k++) {
        float s = __shfl_sync(0xffffffffu, p, k * 4);
        mx = fmaxf(mx, s);
    }
    float sum = 0.0f;
    #pragma unroll
    for (int k = 0; k < 8; k++) {
        float s = __shfl_sync(0xffffffffu, p, k * 4);
        sum += expf(s - mx);
    }
    float w = expf(p - mx) / sum;   // a[e, head(lane)]

    // write attention output (lanes 0,4,...,28 own distinct heads)
    if (a_out && (lane & 3) == 0) {
        __stcs(&a_out[(size_t)gw * 8 + (lane >> 2)], w);   // streaming store
    }

    // scatter eft * a into nft[dst]
    float* dstp = nft + (size_t)d * HD + lane * 4;
    atomicAdd(dstp + 0, ev.x * w);
    atomicAdd(dstp + 1, ev.y * w);
    atomicAdd(dstp + 2, ev.z * w);
    atomicAdd(dstp + 3, ev.w * w);
}

// ---------------------------------------------------------------------------
// Target kernel: one warp per target node.
// x = nft[target] + 1e-15 ; norm over heads per-d: sum_h x[h,d]^2.
// Lane l holds d-values (l&3)*4 .. +3 for head (l>>2). Lanes sharing (l&3)
// hold the same d's across the 8 heads -> butterfly over masks 4,8,16.
// ---------------------------------------------------------------------------
__global__ void target_kernel(const int* __restrict__ tidx,
                              const float* __restrict__ nft,
                              float* __restrict__ out,
                              int T)
{
    int gw   = (blockIdx.x * blockDim.x + threadIdx.x) >> 5;
    int lane = threadIdx.x & 31;
    if (gw >= T) return;

    int nid = __ldg(&tidx[gw]);
    const float4* vp = (const float4*)(nft + (size_t)nid * HD);
    float4 v = vp[lane];
    float4 x;
    x.x = v.x + 1e-15f; x.y = v.y + 1e-15f;
    x.z = v.z + 1e-15f; x.w = v.w + 1e-15f;

    float4 s;
    s.x = x.x * x.x; s.y = x.y * x.y; s.z = x.z * x.z; s.w = x.w * x.w;
    #pragma unroll
    for (int m = 4; m <= 16; m <<= 1) {
        s.x += __shfl_xor_sync(0xffffffffu, s.x, m);
        s.y += __shfl_xor_sync(0xffffffffu, s.y, m);
        s.z += __shfl_xor_sync(0xffffffffu, s.z, m);
        s.w += __shfl_xor_sync(0xffffffffu, s.w, m);
    }
    // s.* = sum over heads of x^2 for each of this lane's 4 d's
    float4 o;
    o.x = x.x / fmaxf(sqrtf(s.x), 1e-12f);
    o.y = x.y / fmaxf(sqrtf(s.y), 1e-12f);
    o.z = x.z / fmaxf(sqrtf(s.z), 1e-12f);
    o.w = x.w / fmaxf(sqrtf(s.w), 1e-12f);

    ((float4*)(out + (size_t)gw * HD))[lane] = o;
}

// ---------------------------------------------------------------------------
extern "C" void kernel_launch(void* const* d_in, const int* in_sizes, int n_in,
                              void* d_out, int out_size)
{
    const float* node = (const float*)d_in[0];   // [N,H,D]
    const float* eft  = (const float*)d_in[1];   // [E,H,D]
    const int*   dst  = (const int*)d_in[2];     // [E]
    const int*   tidx = (const int*)d_in[3];     // [T]

    int N = in_sizes[0] / HD;
    int E = in_sizes[2];
    int T = in_sizes[3];

    float* out   = (float*)d_out;                // [T,H,D]
    float* a_out = nullptr;
    long long need = (long long)T * HD + (long long)E * 8;
    if ((long long)out_size >= need) {
        a_out = out + (size_t)T * HD;            // tuple (out, a): a after out
    }

    void* nft_ptr = nullptr;
    cudaGetSymbolAddress(&nft_ptr, g_nft);
    float* nft = (float*)nft_ptr;

    // zero the segment-sum accumulator (graph-capturable async memset)
    cudaMemsetAsync(nft_ptr, 0, (size_t)N * HD * sizeof(float), 0);

    // one warp per edge
    {
        int warps_per_block = 8;                 // 256 threads
        int blocks = (E + warps_per_block - 1) / warps_per_block;
        edge_kernel<<<blocks, warps_per_block * 32>>>(eft, node, dst, a_out, nft, E);
    }
    // one warp per target
    {
        int warps_per_block = 8;
        int blocks = (T + warps_per_block - 1) / warps_per_block;
        target_kernel<<<blocks, warps_per_block * 32>>>(tidx, nft, out, T);
    }
}

// round 9
// speedup vs baseline: 1.4762x; 1.4762x over previous
#include <cuda_runtime.h>
#include <cuda_bf16.h>
#include <math.h>

// Problem constants (from reference): H=8, D=16 -> HD=128
#define HD 128
#define MAX_N 100000

// Scratch: segment-sum accumulator [N,H,D] (51.2 MB) + target-node flags.
__device__ float         g_nft[(size_t)MAX_N * HD];
__device__ unsigned char g_flag[MAX_N];

// ---------------------------------------------------------------------------
// Mark nodes that appear in target_idx (only their nft rows are ever read).
// ---------------------------------------------------------------------------
__global__ void flag_kernel(const int* __restrict__ tidx,
                            unsigned char* __restrict__ flag, int T)
{
    int i = blockIdx.x * blockDim.x + threadIdx.x;
    if (i < T) flag[__ldg(&tidx[i])] = 1;
}

// ---------------------------------------------------------------------------
// Edge kernel: one warp per edge.
// Lane l holds float4 = elements [l*4, l*4+4) of the 128-wide (h*16+d) row.
// head(l) = l >> 2 ; the 16 elements of one head span 4 consecutive lanes.
// Scatter into nft only when dst is a target node (~18% of edges), and use
// one red.global.add.v4.f32 per lane (16B) instead of 4 scalar atomics.
// ---------------------------------------------------------------------------
__global__ void edge_kernel(const float* __restrict__ eft,
                            const float* __restrict__ node,
                            const int*   __restrict__ dst,
                            const unsigned char* __restrict__ flag,
                            float*       __restrict__ a_out,   // may be null
                            float*       __restrict__ nft,
                            int E)
{
    int gw   = (blockIdx.x * blockDim.x + threadIdx.x) >> 5;   // global warp = edge id
    int lane = threadIdx.x & 31;
    if (gw >= E) return;

    int d = __ldg(&dst[gw]);   // broadcast (same addr all lanes -> L1 broadcast)

    const float4* ep = (const float4*)(eft  + (size_t)gw * HD);
    const float4* np = (const float4*)(node + (size_t)d  * HD);
    float4 ev = __ldcs(ep + lane);   // streaming: read-once, keep L2 for node/nft
    float4 nv = __ldg (np + lane);   // reused across edges -> cache normally

    // per-lane partial dot (4 of the 16 d's of this lane's head)
    float p = ev.x * nv.x + ev.y * nv.y + ev.z * nv.z + ev.w * nv.w;
    // reduce within the 4-lane head group
    p += __shfl_xor_sync(0xffffffffu, p, 1);
    p += __shfl_xor_sync(0xffffffffu, p, 2);
    // p = sim[e, head(lane)] on every lane of the group

    // softmax across the 8 heads (values live on lanes 0,4,8,...,28)
    float mx = p;
    #pragma unroll
    for (int k = 0; k < 8; k++) {
        float s = __shfl_sync(0xffffffffu, p, k * 4);
        mx = fmaxf(mx, s);
    }
    float sum = 0.0f;
    #pragma unroll
    for (int k = 0; k < 8; k++) {
        float s = __shfl_sync(0xffffffffu, p, k * 4);
        sum += expf(s - mx);
    }
    float w = expf(p - mx) / sum;   // a[e, head(lane)]

    // write attention output: gather the 8 head weights into lanes 0..7 for
    // one coalesced 32B store per edge
    if (a_out) {
        float wv = __shfl_sync(0xffffffffu, w, (lane * 4) & 31);
        if (lane < 8) __stcs(&a_out[(size_t)gw * 8 + lane], wv);
    }

    // scatter eft * a into nft[dst] — only if dst is ever read (target node)
    if (__ldg(&flag[d])) {
        float* dstp = nft + (size_t)d * HD + lane * 4;
        asm volatile("red.global.add.v4.f32 [%0], {%1, %2, %3, %4};"
                     :: "l"(dstp),
                        "f"(ev.x * w), "f"(ev.y * w),
                        "f"(ev.z * w), "f"(ev.w * w)
                     : "memory");
    }
}

// ---------------------------------------------------------------------------
// Target kernel: one warp per target node.
// x = nft[target] + 1e-15 ; norm over heads per-d: sum_h x[h,d]^2.
// Lane l holds d-values (l&3)*4 .. +3 for head (l>>2). Lanes sharing (l&3)
// hold the same d's across the 8 heads -> butterfly over masks 4,8,16.
// ---------------------------------------------------------------------------
__global__ void target_kernel(const int* __restrict__ tidx,
                              const float* __restrict__ nft,
                              float* __restrict__ out,
                              int T)
{
    int gw   = (blockIdx.x * blockDim.x + threadIdx.x) >> 5;
    int lane = threadIdx.x & 31;
    if (gw >= T) return;

    int nid = __ldg(&tidx[gw]);
    const float4* vp = (const float4*)(nft + (size_t)nid * HD);
    float4 v = vp[lane];
    float4 x;
    x.x = v.x + 1e-15f; x.y = v.y + 1e-15f;
    x.z = v.z + 1e-15f; x.w = v.w + 1e-15f;

    float4 s;
    s.x = x.x * x.x; s.y = x.y * x.y; s.z = x.z * x.z; s.w = x.w * x.w;
    #pragma unroll
    for (int m = 4; m <= 16; m <<= 1) {
        s.x += __shfl_xor_sync(0xffffffffu, s.x, m);
        s.y += __shfl_xor_sync(0xffffffffu, s.y, m);
        s.z += __shfl_xor_sync(0xffffffffu, s.z, m);
        s.w += __shfl_xor_sync(0xffffffffu, s.w, m);
    }
    // s.* = sum over heads of x^2 for each of this lane's 4 d's
    float4 o;
    o.x = x.x / fmaxf(sqrtf(s.x), 1e-12f);
    o.y = x.y / fmaxf(sqrtf(s.y), 1e-12f);
    o.z = x.z / fmaxf(sqrtf(s.z), 1e-12f);
    o.w = x.w / fmaxf(sqrtf(s.w), 1e-12f);

    ((float4*)(out + (size_t)gw * HD))[lane] = o;
}

// ---------------------------------------------------------------------------
extern "C" void kernel_launch(void* const* d_in, const int* in_sizes, int n_in,
                              void* d_out, int out_size)
{
    const float* node = (const float*)d_in[0];   // [N,H,D]
    const float* eft  = (const float*)d_in[1];   // [E,H,D]
    const int*   dst  = (const int*)d_in[2];     // [E]
    const int*   tidx = (const int*)d_in[3];     // [T]

    int N = in_sizes[0] / HD;
    int E = in_sizes[2];
    int T = in_sizes[3];

    float* out   = (float*)d_out;                // [T,H,D]
    float* a_out = nullptr;
    long long need = (long long)T * HD + (long long)E * 8;
    if ((long long)out_size >= need) {
        a_out = out + (size_t)T * HD;            // tuple (out, a): a after out
    }

    void* nft_ptr = nullptr;
    cudaGetSymbolAddress(&nft_ptr, g_nft);
    float* nft = (float*)nft_ptr;

    void* flag_ptr = nullptr;
    cudaGetSymbolAddress(&flag_ptr, g_flag);
    unsigned char* flag = (unsigned char*)flag_ptr;

    // zero the accumulator + flags (graph-capturable async memsets)
    cudaMemsetAsync(nft_ptr,  0, (size_t)N * HD * sizeof(float), 0);
    cudaMemsetAsync(flag_ptr, 0, (size_t)N, 0);

    // mark target nodes
    flag_kernel<<<(T + 255) / 256, 256>>>(tidx, flag, T);

    // one warp per edge
    {
        int warps_per_block = 8;                 // 256 threads
        int blocks = (E + warps_per_block - 1) / warps_per_block;
        edge_kernel<<<blocks, warps_per_block * 32>>>(eft, node, dst, flag, a_out, nft, E);
    }
    // one warp per target
    {
        int warps_per_block = 8;
        int blocks = (T + warps_per_block - 1) / warps_per_block;
        target_kernel<<<blocks, warps_per_block * 32>>>(tidx, nft, out, T);
    }
}